// round 5
// baseline (speedup 1.0000x reference)
#include <cuda_runtime.h>
#include <cstdint>

#define BATCH 32
#define CH    256
#define HH    56
#define WW    56
#define HW    3136
#define KK2   2304      // CH*9
#define NPAIR (KK2/2)   // 1152
#define MEXP  8

#define BM 128          // o per CTA
#define BN 128          // pixels per CTA
#define BK 32           // k per chunk
#define NCHUNK (KK2 / BK)   // 72

// smem rows: 64B data + 16B pad = 80B stride (conflict-free ldmatrix)
#define ROWB   80
#define TILE_B (128 * ROWB)
#define OFF_AH0 0
#define OFF_AL0 (OFF_AH0 + TILE_B)
#define OFF_BH0 (OFF_AL0 + TILE_B)
#define OFF_BL0 (OFF_BH0 + TILE_B)
#define STAGE   (4 * TILE_B)                // 40960
#define SMEM_BYTES (2 * STAGE)              // 81920

// Scratch
__device__ float    g_gap[BATCH * CH];
__device__ float    g_alpha[BATCH * MEXP];
__device__ float    g_biasc[BATCH * CH];
__device__ uint32_t g_wh[(size_t)BATCH * CH * NPAIR];   // combined weight hi pairs {bf16(k1):bf16(k0)}
__device__ uint32_t g_wl[(size_t)BATCH * CH * NPAIR];   // lo residual pairs
__device__ uint32_t g_xs[(size_t)BATCH * CH * HW];      // x packed per-elem {hi16 : lo16}

// ---------------- helpers ----------------
__device__ __forceinline__ uint32_t smem_u32(const void* p) {
    uint32_t a;
    asm("{ .reg .u64 t; cvta.to.shared.u64 t, %1; cvt.u32.u64 %0, t; }" : "=r"(a) : "l"(p));
    return a;
}
__device__ __forceinline__ void split2(float x0, float x1, uint32_t& h, uint32_t& l) {
    asm("cvt.rn.bf16x2.f32 %0, %1, %2;" : "=r"(h) : "f"(x1), "f"(x0));
    float r0 = x0 - __uint_as_float(h << 16);
    float r1 = x1 - __uint_as_float(h & 0xffff0000u);
    asm("cvt.rn.bf16x2.f32 %0, %1, %2;" : "=r"(l) : "f"(r1), "f"(r0));
}
__device__ __forceinline__ void ldsm4(uint32_t& r0, uint32_t& r1, uint32_t& r2, uint32_t& r3,
                                      uint32_t addr) {
    asm volatile("ldmatrix.sync.aligned.m8n8.x4.shared.b16 {%0,%1,%2,%3}, [%4];"
                 : "=r"(r0), "=r"(r1), "=r"(r2), "=r"(r3) : "r"(addr));
}
__device__ __forceinline__ void mma16816(float* c, const uint32_t* a, uint32_t b0, uint32_t b1) {
    asm volatile(
        "mma.sync.aligned.m16n8k16.row.col.f32.bf16.bf16.f32 "
        "{%0,%1,%2,%3}, {%4,%5,%6,%7}, {%8,%9}, {%0,%1,%2,%3};"
        : "+f"(c[0]), "+f"(c[1]), "+f"(c[2]), "+f"(c[3])
        : "r"(a[0]), "r"(a[1]), "r"(a[2]), "r"(a[3]), "r"(b0), "r"(b1));
}
__device__ __forceinline__ void cpasync16(uint32_t dst, const void* src) {
    asm volatile("cp.async.cg.shared.global [%0], [%1], 16;" :: "r"(dst), "l"(src) : "memory");
}

// ---------------------------------------------------------------------------
// 1) Global average pool
// ---------------------------------------------------------------------------
__global__ void gap_kernel(const float* __restrict__ x) {
    int bc = blockIdx.x;
    const float* p = x + (size_t)bc * HW;
    float s = 0.f;
    for (int i = threadIdx.x; i < HW; i += 128) s += p[i];
    __shared__ float sm[4];
    #pragma unroll
    for (int off = 16; off; off >>= 1) s += __shfl_down_sync(0xffffffffu, s, off);
    if ((threadIdx.x & 31) == 0) sm[threadIdx.x >> 5] = s;
    __syncthreads();
    if (threadIdx.x == 0)
        g_gap[bc] = (sm[0] + sm[1] + sm[2] + sm[3]) * (1.f / (float)HW);
}

// ---------------------------------------------------------------------------
// 2) Gate softmax + combined bias
// ---------------------------------------------------------------------------
__global__ void gate_kernel(const float* __restrict__ gate_w,
                            const float* __restrict__ gate_b,
                            const float* __restrict__ bias) {
    __shared__ float lg[BATCH][MEXP];
    __shared__ float al[BATCH][MEXP];
    int t = threadIdx.x;
    int b = t >> 3, m = t & 7;
    float acc = gate_b[m];
    const float* gp = &g_gap[b * CH];
    const float* gw = &gate_w[m * CH];
    for (int i = 0; i < CH; i++) acc += gp[i] * gw[i];
    lg[b][m] = acc;
    __syncthreads();
    if (t < BATCH) {
        float mx = lg[t][0];
        #pragma unroll
        for (int j = 1; j < MEXP; j++) mx = fmaxf(mx, lg[t][j]);
        float e[MEXP], s = 0.f;
        #pragma unroll
        for (int j = 0; j < MEXP; j++) { e[j] = expf(lg[t][j] - mx); s += e[j]; }
        float inv = 1.f / s;
        #pragma unroll
        for (int j = 0; j < MEXP; j++) { al[t][j] = e[j] * inv; g_alpha[t * MEXP + j] = e[j] * inv; }
    }
    __syncthreads();
    for (int b2 = 0; b2 < BATCH; b2++) {
        float s = 0.f;
        #pragma unroll
        for (int j = 0; j < MEXP; j++) s += al[b2][j] * bias[j * CH + t];
        g_biasc[b2 * CH + t] = s;
    }
}

// ---------------------------------------------------------------------------
// 3) Combine experts + pre-split to bf16 hi/lo pair words
// ---------------------------------------------------------------------------
__global__ void combine_kernel(const float* __restrict__ weight) {
    int b = blockIdx.y;
    size_t i4 = (size_t)blockIdx.x * 256 + threadIdx.x;   // float4 index within sample
    float a[MEXP];
    #pragma unroll
    for (int m = 0; m < MEXP; m++) a[m] = g_alpha[b * MEXP + m];
    float4 acc = make_float4(0.f, 0.f, 0.f, 0.f);
    #pragma unroll
    for (int m = 0; m < MEXP; m++) {
        const float4 v = ((const float4*)(weight + (size_t)m * CH * KK2))[i4];
        acc.x += a[m] * v.x; acc.y += a[m] * v.y;
        acc.z += a[m] * v.z; acc.w += a[m] * v.w;
    }
    uint32_t h0, l0, h1, l1;
    split2(acc.x, acc.y, h0, l0);
    split2(acc.z, acc.w, h1, l1);
    ((uint2*)(g_wh + (size_t)b * CH * NPAIR))[i4] = make_uint2(h0, h1);
    ((uint2*)(g_wl + (size_t)b * CH * NPAIR))[i4] = make_uint2(l0, l1);
}

// ---------------------------------------------------------------------------
// 3b) Pre-split x: packed = (bf16hi << 16) | bf16lo  per element
// ---------------------------------------------------------------------------
__global__ void xsplit_kernel(const float* __restrict__ x) {
    size_t i4 = (size_t)blockIdx.x * 256 + threadIdx.x;
    float4 v = ((const float4*)x)[i4];
    uint32_t h0, l0, h1, l1;
    split2(v.x, v.y, h0, l0);
    split2(v.z, v.w, h1, l1);
    uint4 o;
    o.x = __byte_perm(l0, h0, 0x5410);   // {hi(x), lo(x)}
    o.y = __byte_perm(l0, h0, 0x7632);   // {hi(y), lo(y)}
    o.z = __byte_perm(l1, h1, 0x5410);
    o.w = __byte_perm(l1, h1, 0x7632);
    ((uint4*)g_xs)[i4] = o;
}

// ---------------------------------------------------------------------------
// 4) Conv GEMM: mma.sync bf16 3-term; all conversions pre-done.
//    grid (25, 2, 32), 256 threads, warps 4(m) x 2(n).
// ---------------------------------------------------------------------------
__global__ void __launch_bounds__(256, 1)
conv_mma_kernel(float* __restrict__ out) {
    extern __shared__ char smem[];
    const uint32_t sbase = smem_u32(smem);
    const int tid  = threadIdx.x;
    const int wid  = tid >> 5;
    const int lane = tid & 31;
    const int warp_m = wid >> 1;
    const int warp_n = wid & 1;

    const int b  = blockIdx.z;
    const int o0 = blockIdx.y * BM;
    const int p0 = blockIdx.x * BN;

    // A producer: thread -> (row ar, 32B half seg) ; cp.async 2x16B per array
    const int ar  = tid >> 1;
    const int seg = tid & 1;
    const uint32_t* whRow = g_wh + ((size_t)(b * CH) + o0 + ar) * NPAIR + seg * 8;
    const uint32_t* wlRow = g_wl + ((size_t)(b * CH) + o0 + ar) * NPAIR + seg * 8;
    const uint32_t aDst = (uint32_t)ar * ROWB + seg * 32;

    // B producer: warp owns k = kc + wid*4..+3 ; lane+32j = pixel row
    int hj[4], wj[4]; bool vj[4];
    #pragma unroll
    for (int j = 0; j < 4; j++) {
        int p = p0 + lane + 32 * j;
        vj[j] = p < HW;
        int pp = vj[j] ? p : 0;
        hj[j] = pp / WW;
        wj[j] = pp - hj[j] * WW;
    }
    const uint32_t* xb = g_xs + (size_t)b * CH * HW;

    const uint32_t aRow = (uint32_t)(warp_m * 32 + (lane & 15)) * ROWB + ((lane >> 4) * 16);
    const uint32_t bRow = (uint32_t)(warp_n * 64 + (lane & 15)) * ROWB + ((lane >> 4) * 16);

    float acc[2][8][4];
    #pragma unroll
    for (int t = 0; t < 2; t++)
        #pragma unroll
        for (int j = 0; j < 8; j++)
            #pragma unroll
            for (int q = 0; q < 4; q++) acc[t][j][q] = 0.f;

    uint32_t v[16];

    auto issueA = [&](int chunk, int s) {
        const uint32_t d = sbase + s * STAGE + aDst;
        const uint32_t* sh = whRow + chunk * 16;
        const uint32_t* sl = wlRow + chunk * 16;
        cpasync16(d + OFF_AH0,      sh);
        cpasync16(d + OFF_AH0 + 16, sh + 4);
        cpasync16(d + OFF_AL0,      sl);
        cpasync16(d + OFF_AL0 + 16, sl + 4);
        asm volatile("cp.async.commit_group;" ::: "memory");
    };
    auto gatherB = [&](int chunk) {
        const int kb = chunk * BK + wid * 4;
        int cc[4], dh[4], dw[4];
        #pragma unroll
        for (int kk = 0; kk < 4; kk++) {
            int k = kb + kk;
            cc[kk] = k / 9;
            int r = k - cc[kk] * 9;
            int r3 = r / 3;
            dh[kk] = r3 - 1;
            dw[kk] = r - r3 * 3 - 1;
        }
        #pragma unroll
        for (int j = 0; j < 4; j++)
            #pragma unroll
            for (int kk = 0; kk < 4; kk++) {
                int ih = hj[j] + dh[kk];
                int iw = wj[j] + dw[kk];
                bool ok = vj[j] && ((unsigned)ih < HH) && ((unsigned)iw < WW);
                v[j * 4 + kk] = ok ? xb[(size_t)cc[kk] * HW + ih * WW + iw] : 0u;
            }
    };
    auto storeB = [&](int s) {
        char* sb = smem + s * STAGE;
        #pragma unroll
        for (int j = 0; j < 4; j++) {
            uint32_t bh0 = __byte_perm(v[j * 4 + 0], v[j * 4 + 1], 0x7632);
            uint32_t bl0 = __byte_perm(v[j * 4 + 0], v[j * 4 + 1], 0x5410);
            uint32_t bh1 = __byte_perm(v[j * 4 + 2], v[j * 4 + 3], 0x7632);
            uint32_t bl1 = __byte_perm(v[j * 4 + 2], v[j * 4 + 3], 0x5410);
            uint32_t boff = (uint32_t)(lane + 32 * j) * ROWB + wid * 8;
            *(uint2*)(sb + OFF_BH0 + boff) = make_uint2(bh0, bh1);
            *(uint2*)(sb + OFF_BL0 + boff) = make_uint2(bl0, bl1);
        }
    };

    // ---- prologue ----
    issueA(0, 0);
    gatherB(0);
    storeB(0);
    asm volatile("cp.async.wait_group 0;" ::: "memory");
    __syncthreads();

    for (int c0 = 0; c0 < NCHUNK; c0++) {
        const int s = c0 & 1;
        const bool more = (c0 + 1 < NCHUNK);
        if (more) { issueA(c0 + 1, s ^ 1); gatherB(c0 + 1); }

        const uint32_t sAh = sbase + s * STAGE + OFF_AH0 + aRow;
        const uint32_t sAl = sbase + s * STAGE + OFF_AL0 + aRow;
        const uint32_t sBh = sbase + s * STAGE + OFF_BH0 + bRow;
        const uint32_t sBl = sbase + s * STAGE + OFF_BL0 + bRow;

        #pragma unroll
        for (int kk = 0; kk < 2; kk++) {
            uint32_t ah[2][4], al_[2][4], bh[4][4], bl[4][4];
            #pragma unroll
            for (int t = 0; t < 2; t++) {
                ldsm4(ah[t][0], ah[t][1], ah[t][2], ah[t][3], sAh + t * (16 * ROWB) + kk * 32);
                ldsm4(al_[t][0], al_[t][1], al_[t][2], al_[t][3], sAl + t * (16 * ROWB) + kk * 32);
            }
            #pragma unroll
            for (int nb = 0; nb < 4; nb++) {
                ldsm4(bh[nb][0], bh[nb][1], bh[nb][2], bh[nb][3], sBh + nb * (16 * ROWB) + kk * 32);
                ldsm4(bl[nb][0], bl[nb][1], bl[nb][2], bl[nb][3], sBl + nb * (16 * ROWB) + kk * 32);
            }
            // term-major ordering: 16 independent MMAs between accumulator reuses
            #pragma unroll
            for (int t = 0; t < 2; t++)
                #pragma unroll
                for (int nb = 0; nb < 4; nb++) {
                    mma16816(acc[t][2 * nb],     ah[t], bh[nb][0], bh[nb][2]);
                    mma16816(acc[t][2 * nb + 1], ah[t], bh[nb][1], bh[nb][3]);
                }
            #pragma unroll
            for (int t = 0; t < 2; t++)
                #pragma unroll
                for (int nb = 0; nb < 4; nb++) {
                    mma16816(acc[t][2 * nb],     ah[t], bl[nb][0], bl[nb][2]);
                    mma16816(acc[t][2 * nb + 1], ah[t], bl[nb][1], bl[nb][3]);
                }
            #pragma unroll
            for (int t = 0; t < 2; t++)
                #pragma unroll
                for (int nb = 0; nb < 4; nb++) {
                    mma16816(acc[t][2 * nb],     al_[t], bh[nb][0], bh[nb][2]);
                    mma16816(acc[t][2 * nb + 1], al_[t], bh[nb][1], bh[nb][3]);
                }
        }
        if (more) storeB(s ^ 1);
        asm volatile("cp.async.wait_group 0;" ::: "memory");
        __syncthreads();
    }

    // ---- epilogue ----
    #pragma unroll
    for (int t = 0; t < 2; t++) {
        int r0 = o0 + warp_m * 32 + t * 16 + (lane >> 2);
        float bi0 = g_biasc[b * CH + r0];
        float bi1 = g_biasc[b * CH + r0 + 8];
        float* out0 = out + ((size_t)b * CH + r0) * HW;
        float* out1 = out0 + 8 * HW;
        #pragma unroll
        for (int j = 0; j < 8; j++) {
            int p = p0 + warp_n * 64 + j * 8 + (lane & 3) * 2;
            if (p < HW) {
                *(float2*)(out0 + p) = make_float2(acc[t][j][0] + bi0, acc[t][j][1] + bi0);
                *(float2*)(out1 + p) = make_float2(acc[t][j][2] + bi1, acc[t][j][3] + bi1);
            }
        }
    }
}

// ---------------------------------------------------------------------------
extern "C" void kernel_launch(void* const* d_in, const int* in_sizes, int n_in,
                              void* d_out, int out_size) {
    const float* x      = (const float*)d_in[0];
    const float* weight = (const float*)d_in[1];
    const float* bias   = (const float*)d_in[2];
    const float* gate_w = (const float*)d_in[3];
    const float* gate_b = (const float*)d_in[4];
    float* out = (float*)d_out;

    cudaFuncSetAttribute(conv_mma_kernel,
                         cudaFuncAttributeMaxDynamicSharedMemorySize, SMEM_BYTES);

    gap_kernel<<<BATCH * CH, 128>>>(x);
    gate_kernel<<<1, 256>>>(gate_w, gate_b, bias);
    combine_kernel<<<dim3(CH * KK2 / 4 / 256, BATCH), 256>>>(weight);
    xsplit_kernel<<<(int)((size_t)BATCH * CH * HW / 4 / 256), 256>>>(x);
    conv_mma_kernel<<<dim3((HW + BN - 1) / BN, CH / BM, BATCH), 256, SMEM_BYTES>>>(out);
}

// round 6
// speedup vs baseline: 1.0376x; 1.0376x over previous
#include <cuda_runtime.h>
#include <cstdint>

#define BATCH 32
#define CH    256
#define HH    56
#define WW    56
#define HW    3136
#define KK2   2304      // CH*9
#define NPAIR (KK2/2)   // 1152
#define MEXP  8

#define BM 128          // o per CTA
#define BN 64           // pixels per CTA (49*64 = 3136 exact)
#define BK 32           // k per chunk
#define NCHUNK (KK2 / BK)   // 72

// smem rows: 64B data + 16B pad = 80B stride (conflict-free ldmatrix)
#define ROWB   80
#define ATILE  (128 * ROWB)     // 10240
#define BTILE  (64 * ROWB)      // 5120
#define OFF_AH0 0
#define OFF_AL0 (OFF_AH0 + ATILE)
#define OFF_BH0 (OFF_AL0 + ATILE)
#define OFF_BL0 (OFF_BH0 + BTILE)
#define STAGE   (OFF_BL0 + BTILE)           // 30720
#define SMEM_BYTES (2 * STAGE)              // 61440

// Scratch
__device__ float    g_gap[BATCH * CH];
__device__ float    g_alpha[BATCH * MEXP];
__device__ float    g_biasc[BATCH * CH];
__device__ uint32_t g_wh[(size_t)BATCH * CH * NPAIR];   // combined weight hi pairs {bf16(k1):bf16(k0)}
__device__ uint32_t g_wl[(size_t)BATCH * CH * NPAIR];   // lo residual pairs
__device__ uint32_t g_xs[(size_t)BATCH * CH * HW];      // x packed per-elem {hi16 : lo16}

// ---------------- helpers ----------------
__device__ __forceinline__ uint32_t smem_u32(const void* p) {
    uint32_t a;
    asm("{ .reg .u64 t; cvta.to.shared.u64 t, %1; cvt.u32.u64 %0, t; }" : "=r"(a) : "l"(p));
    return a;
}
__device__ __forceinline__ void split2(float x0, float x1, uint32_t& h, uint32_t& l) {
    asm("cvt.rn.bf16x2.f32 %0, %1, %2;" : "=r"(h) : "f"(x1), "f"(x0));
    float r0 = x0 - __uint_as_float(h << 16);
    float r1 = x1 - __uint_as_float(h & 0xffff0000u);
    asm("cvt.rn.bf16x2.f32 %0, %1, %2;" : "=r"(l) : "f"(r1), "f"(r0));
}
__device__ __forceinline__ void ldsm4(uint32_t& r0, uint32_t& r1, uint32_t& r2, uint32_t& r3,
                                      uint32_t addr) {
    asm volatile("ldmatrix.sync.aligned.m8n8.x4.shared.b16 {%0,%1,%2,%3}, [%4];"
                 : "=r"(r0), "=r"(r1), "=r"(r2), "=r"(r3) : "r"(addr));
}
__device__ __forceinline__ void mma16816(float* c, const uint32_t* a, uint32_t b0, uint32_t b1) {
    asm volatile(
        "mma.sync.aligned.m16n8k16.row.col.f32.bf16.bf16.f32 "
        "{%0,%1,%2,%3}, {%4,%5,%6,%7}, {%8,%9}, {%0,%1,%2,%3};"
        : "+f"(c[0]), "+f"(c[1]), "+f"(c[2]), "+f"(c[3])
        : "r"(a[0]), "r"(a[1]), "r"(a[2]), "r"(a[3]), "r"(b0), "r"(b1));
}
__device__ __forceinline__ void cpasync16(uint32_t dst, const void* src) {
    asm volatile("cp.async.cg.shared.global [%0], [%1], 16;" :: "r"(dst), "l"(src) : "memory");
}

// ---------------------------------------------------------------------------
// 1) Global average pool
// ---------------------------------------------------------------------------
__global__ void gap_kernel(const float* __restrict__ x) {
    int bc = blockIdx.x;
    const float* p = x + (size_t)bc * HW;
    float s = 0.f;
    for (int i = threadIdx.x; i < HW; i += 128) s += p[i];
    __shared__ float sm[4];
    #pragma unroll
    for (int off = 16; off; off >>= 1) s += __shfl_down_sync(0xffffffffu, s, off);
    if ((threadIdx.x & 31) == 0) sm[threadIdx.x >> 5] = s;
    __syncthreads();
    if (threadIdx.x == 0)
        g_gap[bc] = (sm[0] + sm[1] + sm[2] + sm[3]) * (1.f / (float)HW);
}

// ---------------------------------------------------------------------------
// 2) Gate softmax + combined bias
// ---------------------------------------------------------------------------
__global__ void gate_kernel(const float* __restrict__ gate_w,
                            const float* __restrict__ gate_b,
                            const float* __restrict__ bias) {
    __shared__ float lg[BATCH][MEXP];
    __shared__ float al[BATCH][MEXP];
    int t = threadIdx.x;
    int b = t >> 3, m = t & 7;
    float acc = gate_b[m];
    const float* gp = &g_gap[b * CH];
    const float* gw = &gate_w[m * CH];
    for (int i = 0; i < CH; i++) acc += gp[i] * gw[i];
    lg[b][m] = acc;
    __syncthreads();
    if (t < BATCH) {
        float mx = lg[t][0];
        #pragma unroll
        for (int j = 1; j < MEXP; j++) mx = fmaxf(mx, lg[t][j]);
        float e[MEXP], s = 0.f;
        #pragma unroll
        for (int j = 0; j < MEXP; j++) { e[j] = expf(lg[t][j] - mx); s += e[j]; }
        float inv = 1.f / s;
        #pragma unroll
        for (int j = 0; j < MEXP; j++) { al[t][j] = e[j] * inv; g_alpha[t * MEXP + j] = e[j] * inv; }
    }
    __syncthreads();
    for (int b2 = 0; b2 < BATCH; b2++) {
        float s = 0.f;
        #pragma unroll
        for (int j = 0; j < MEXP; j++) s += al[b2][j] * bias[j * CH + t];
        g_biasc[b2 * CH + t] = s;
    }
}

// ---------------------------------------------------------------------------
// 3) Combine experts + pre-split to bf16 hi/lo pair words
// ---------------------------------------------------------------------------
__global__ void combine_kernel(const float* __restrict__ weight) {
    int b = blockIdx.y;
    size_t i4 = (size_t)blockIdx.x * 256 + threadIdx.x;
    float a[MEXP];
    #pragma unroll
    for (int m = 0; m < MEXP; m++) a[m] = g_alpha[b * MEXP + m];
    float4 acc = make_float4(0.f, 0.f, 0.f, 0.f);
    #pragma unroll
    for (int m = 0; m < MEXP; m++) {
        const float4 v = ((const float4*)(weight + (size_t)m * CH * KK2))[i4];
        acc.x += a[m] * v.x; acc.y += a[m] * v.y;
        acc.z += a[m] * v.z; acc.w += a[m] * v.w;
    }
    uint32_t h0, l0, h1, l1;
    split2(acc.x, acc.y, h0, l0);
    split2(acc.z, acc.w, h1, l1);
    ((uint2*)(g_wh + (size_t)b * CH * NPAIR))[i4] = make_uint2(h0, h1);
    ((uint2*)(g_wl + (size_t)b * CH * NPAIR))[i4] = make_uint2(l0, l1);
}

// ---------------------------------------------------------------------------
// 3b) Pre-split x: packed = (bf16hi << 16) | bf16lo  per element
// ---------------------------------------------------------------------------
__global__ void xsplit_kernel(const float* __restrict__ x) {
    size_t i4 = (size_t)blockIdx.x * 256 + threadIdx.x;
    float4 v = ((const float4*)x)[i4];
    uint32_t h0, l0, h1, l1;
    split2(v.x, v.y, h0, l0);
    split2(v.z, v.w, h1, l1);
    uint4 o;
    o.x = __byte_perm(l0, h0, 0x5410);
    o.y = __byte_perm(l0, h0, 0x7632);
    o.z = __byte_perm(l1, h1, 0x5410);
    o.w = __byte_perm(l1, h1, 0x7632);
    ((uint4*)g_xs)[i4] = o;
}

// ---------------------------------------------------------------------------
// 4) Conv GEMM: mma.sync bf16 3-term. Tiles 128(o) x 64(pix) x 32(k).
//    grid (49, 2, 32), 256 threads = 8 warps, warp tile m16 x n64.
//    2 CTAs / SM.
// ---------------------------------------------------------------------------
__global__ void __launch_bounds__(256, 2)
conv_mma_kernel(float* __restrict__ out) {
    extern __shared__ char smem[];
    const uint32_t sbase = smem_u32(smem);
    const int tid  = threadIdx.x;
    const int wid  = tid >> 5;          // warp_m 0..7 -> m offset *16
    const int lane = tid & 31;

    const int b  = blockIdx.z;
    const int o0 = blockIdx.y * BM;
    const int p0 = blockIdx.x * BN;

    // A producer: thread -> (row ar, 32B half seg); cp.async 2x16B per array
    const int ar  = tid >> 1;
    const int seg = tid & 1;
    const uint32_t* whRow = g_wh + ((size_t)(b * CH) + o0 + ar) * NPAIR + seg * 8;
    const uint32_t* wlRow = g_wl + ((size_t)(b * CH) + o0 + ar) * NPAIR + seg * 8;
    const uint32_t aDst = (uint32_t)ar * ROWB + seg * 32;

    // B producer: warp owns k = kc + wid*4..+3 ; lane+32j = pixel row (j<2)
    int hj[2], wj[2];
    #pragma unroll
    for (int j = 0; j < 2; j++) {
        int p = p0 + lane + 32 * j;      // always < HW (49*64 exact)
        hj[j] = p / WW;
        wj[j] = p - hj[j] * WW;
    }
    const uint32_t* xb = g_xs + (size_t)b * CH * HW;

    const uint32_t aRow = (uint32_t)(wid * 16 + (lane & 15)) * ROWB + ((lane >> 4) * 16);
    const uint32_t bRow = (uint32_t)(lane & 15) * ROWB + ((lane >> 4) * 16);

    float acc[8][4];
    #pragma unroll
    for (int j = 0; j < 8; j++)
        #pragma unroll
        for (int q = 0; q < 4; q++) acc[j][q] = 0.f;

    uint32_t v[8];

    auto issueA = [&](int chunk, int s) {
        const uint32_t d = sbase + s * STAGE + aDst;
        const uint32_t* sh = whRow + chunk * 16;
        const uint32_t* sl = wlRow + chunk * 16;
        cpasync16(d + OFF_AH0,      sh);
        cpasync16(d + OFF_AH0 + 16, sh + 4);
        cpasync16(d + OFF_AL0,      sl);
        cpasync16(d + OFF_AL0 + 16, sl + 4);
        asm volatile("cp.async.commit_group;" ::: "memory");
    };
    auto gatherB = [&](int chunk) {
        const int kb = chunk * BK + wid * 4;
        int cc[4], dh[4], dw[4];
        #pragma unroll
        for (int kk = 0; kk < 4; kk++) {
            int k = kb + kk;
            cc[kk] = k / 9;
            int r = k - cc[kk] * 9;
            int r3 = r / 3;
            dh[kk] = r3 - 1;
            dw[kk] = r - r3 * 3 - 1;
        }
        #pragma unroll
        for (int j = 0; j < 2; j++)
            #pragma unroll
            for (int kk = 0; kk < 4; kk++) {
                int ih = hj[j] + dh[kk];
                int iw = wj[j] + dw[kk];
                bool ok = ((unsigned)ih < HH) && ((unsigned)iw < WW);
                v[j * 4 + kk] = ok ? xb[(size_t)cc[kk] * HW + ih * WW + iw] : 0u;
            }
    };
    auto storeB = [&](int s) {
        char* sb = smem + s * STAGE;
        #pragma unroll
        for (int j = 0; j < 2; j++) {
            uint32_t bh0 = __byte_perm(v[j * 4 + 0], v[j * 4 + 1], 0x7632);
            uint32_t bl0 = __byte_perm(v[j * 4 + 0], v[j * 4 + 1], 0x5410);
            uint32_t bh1 = __byte_perm(v[j * 4 + 2], v[j * 4 + 3], 0x7632);
            uint32_t bl1 = __byte_perm(v[j * 4 + 2], v[j * 4 + 3], 0x5410);
            uint32_t boff = (uint32_t)(lane + 32 * j) * ROWB + wid * 8;
            *(uint2*)(sb + OFF_BH0 + boff) = make_uint2(bh0, bh1);
            *(uint2*)(sb + OFF_BL0 + boff) = make_uint2(bl0, bl1);
        }
    };

    // ---- prologue ----
    issueA(0, 0);
    gatherB(0);
    storeB(0);
    asm volatile("cp.async.wait_group 0;" ::: "memory");
    __syncthreads();

    for (int c0 = 0; c0 < NCHUNK; c0++) {
        const int s = c0 & 1;
        const bool more = (c0 + 1 < NCHUNK);
        if (more) { issueA(c0 + 1, s ^ 1); gatherB(c0 + 1); }

        const uint32_t sAh = sbase + s * STAGE + OFF_AH0 + aRow;
        const uint32_t sAl = sbase + s * STAGE + OFF_AL0 + aRow;
        const uint32_t sBh = sbase + s * STAGE + OFF_BH0 + bRow;
        const uint32_t sBl = sbase + s * STAGE + OFF_BL0 + bRow;

        #pragma unroll
        for (int kk = 0; kk < 2; kk++) {
            uint32_t ah[4], al_[4], bh[4][4], bl[4][4];
            ldsm4(ah[0], ah[1], ah[2], ah[3], sAh + kk * 32);
            ldsm4(al_[0], al_[1], al_[2], al_[3], sAl + kk * 32);
            #pragma unroll
            for (int nb = 0; nb < 4; nb++) {
                ldsm4(bh[nb][0], bh[nb][1], bh[nb][2], bh[nb][3], sBh + nb * (16 * ROWB) + kk * 32);
                ldsm4(bl[nb][0], bl[nb][1], bl[nb][2], bl[nb][3], sBl + nb * (16 * ROWB) + kk * 32);
            }
            // term-major: 8 independent MMAs between accumulator reuses
            #pragma unroll
            for (int nb = 0; nb < 4; nb++) {
                mma16816(acc[2 * nb],     ah, bh[nb][0], bh[nb][2]);
                mma16816(acc[2 * nb + 1], ah, bh[nb][1], bh[nb][3]);
            }
            #pragma unroll
            for (int nb = 0; nb < 4; nb++) {
                mma16816(acc[2 * nb],     ah, bl[nb][0], bl[nb][2]);
                mma16816(acc[2 * nb + 1], ah, bl[nb][1], bl[nb][3]);
            }
            #pragma unroll
            for (int nb = 0; nb < 4; nb++) {
                mma16816(acc[2 * nb],     al_, bh[nb][0], bh[nb][2]);
                mma16816(acc[2 * nb + 1], al_, bh[nb][1], bh[nb][3]);
            }
        }
        if (more) storeB(s ^ 1);
        asm volatile("cp.async.wait_group 0;" ::: "memory");
        __syncthreads();
    }

    // ---- epilogue ----
    {
        int r0 = o0 + wid * 16 + (lane >> 2);
        float bi0 = g_biasc[b * CH + r0];
        float bi1 = g_biasc[b * CH + r0 + 8];
        float* out0 = out + ((size_t)b * CH + r0) * HW;
        float* out1 = out0 + 8 * HW;
        #pragma unroll
        for (int j = 0; j < 8; j++) {
            int p = p0 + j * 8 + (lane & 3) * 2;
            *(float2*)(out0 + p) = make_float2(acc[j][0] + bi0, acc[j][1] + bi0);
            *(float2*)(out1 + p) = make_float2(acc[j][2] + bi1, acc[j][3] + bi1);
        }
    }
}

// ---------------------------------------------------------------------------
extern "C" void kernel_launch(void* const* d_in, const int* in_sizes, int n_in,
                              void* d_out, int out_size) {
    const float* x      = (const float*)d_in[0];
    const float* weight = (const float*)d_in[1];
    const float* bias   = (const float*)d_in[2];
    const float* gate_w = (const float*)d_in[3];
    const float* gate_b = (const float*)d_in[4];
    float* out = (float*)d_out;

    cudaFuncSetAttribute(conv_mma_kernel,
                         cudaFuncAttributeMaxDynamicSharedMemorySize, SMEM_BYTES);

    gap_kernel<<<BATCH * CH, 128>>>(x);
    gate_kernel<<<1, 256>>>(gate_w, gate_b, bias);
    combine_kernel<<<dim3(CH * KK2 / 4 / 256, BATCH), 256>>>(weight);
    xsplit_kernel<<<(int)((size_t)BATCH * CH * HW / 4 / 256), 256>>>(x);
    conv_mma_kernel<<<dim3(HW / BN, CH / BM, BATCH), 256, SMEM_BYTES>>>(out);
}